// round 3
// baseline (speedup 1.0000x reference)
#include <cuda_runtime.h>
#include <cstdint>

#define NPIX   6400
#define SCALE  0.17677669529663687f   // 32^-0.5

typedef unsigned long long ull;

// Scratch (device globals), channel-major layouts
__device__ float g_qkv [4 * 768 * 6400];   // [b][o][n]
__device__ float g_attn[4 * 256 * 6400];   // [b][ch][n]

// ---------------------------------------------------------------------------
// Packed fp32x2 helpers (Blackwell dual-FMA pipe)
// ---------------------------------------------------------------------------
__device__ __forceinline__ ull pack_dup(float x) {
    ull r;
    asm("mov.b64 %0, {%1, %1};" : "=l"(r) : "f"(x));
    return r;
}
__device__ __forceinline__ void fma2(ull& d, ull a, ull b) {
    asm("fma.rn.f32x2 %0, %1, %2, %0;" : "+l"(d) : "l"(a), "l"(b));
}
__device__ __forceinline__ void unpack2(float& lo, float& hi, ull v) {
    asm("mov.b64 {%0, %1}, %2;" : "=f"(lo), "=f"(hi) : "l"(v));
}

// ---------------------------------------------------------------------------
// Kernel A: qkv[b][o][n] = sum_c w_qkv[o][c] * y[b][c][n]
// 128x128x16 tile, 256 threads, 8x8 micro-tile with f32x2 packing,
// register-prefetch double buffering over the 16 K-tiles.
// ---------------------------------------------------------------------------
__global__ __launch_bounds__(256) void qkv_gemm(const float* __restrict__ rgb,
                                                const float* __restrict__ ir,
                                                const float* __restrict__ w)
{
    __shared__ float As[16][128];   // As[k][m] = w[m0+m, k0+k]
    __shared__ float Bs[16][128];   // Bs[k][n] = y[b, k0+k, n0+n]

    const int b  = blockIdx.z;
    const int n0 = blockIdx.x * 128;
    const int m0 = blockIdx.y * 128;
    const int tid = threadIdx.x;
    const int tm = (tid >> 4) * 8;
    const int tn = (tid & 15) * 8;

    const float* rb = rgb + (size_t)b * 128 * NPIX;
    const float* ib = ir  + (size_t)b * 128 * NPIX;

    // Per-thread load coordinates (2 chunks for A, 2 for B)
    const int a_row0 = (tid * 2) >> 2,      a_col0 = ((tid * 2) & 3) * 4;
    const int a_row1 = (tid * 2 + 1) >> 2,  a_col1 = ((tid * 2 + 1) & 3) * 4;
    const int b_kr0 = (tid * 2) >> 5,       b_nc0 = ((tid * 2) & 31) * 4;
    const int b_kr1 = (tid * 2 + 1) >> 5,   b_nc1 = ((tid * 2 + 1) & 31) * 4;

    ull acc[8][4];
    #pragma unroll
    for (int i = 0; i < 8; i++)
        #pragma unroll
        for (int j = 0; j < 4; j++) acc[i][j] = 0ull;

    // ---- load K-tile 0 ----
    {
        float4 va0 = *(const float4*)(w + (size_t)(m0 + a_row0) * 256 + a_col0);
        float4 va1 = *(const float4*)(w + (size_t)(m0 + a_row1) * 256 + a_col1);
        As[a_col0 + 0][a_row0] = va0.x; As[a_col0 + 1][a_row0] = va0.y;
        As[a_col0 + 2][a_row0] = va0.z; As[a_col0 + 3][a_row0] = va0.w;
        As[a_col1 + 0][a_row1] = va1.x; As[a_col1 + 1][a_row1] = va1.y;
        As[a_col1 + 2][a_row1] = va1.z; As[a_col1 + 3][a_row1] = va1.w;
        const float* s0 = (b_kr0 < 128) ? (rb + (size_t)b_kr0 * NPIX + n0 + b_nc0)
                                        : (ib + (size_t)(b_kr0 - 128) * NPIX + n0 + b_nc0);
        const float* s1 = (b_kr1 < 128) ? (rb + (size_t)b_kr1 * NPIX + n0 + b_nc1)
                                        : (ib + (size_t)(b_kr1 - 128) * NPIX + n0 + b_nc1);
        *(float4*)&Bs[b_kr0][b_nc0] = *(const float4*)s0;
        *(float4*)&Bs[b_kr1][b_nc1] = *(const float4*)s1;
    }
    __syncthreads();

    for (int kt = 0; kt < 16; kt++) {
        // ---- prefetch next K-tile into registers ----
        float4 pa0, pa1, pb0, pb1;
        if (kt < 15) {
            const int k0 = (kt + 1) * 16;
            pa0 = *(const float4*)(w + (size_t)(m0 + a_row0) * 256 + k0 + a_col0);
            pa1 = *(const float4*)(w + (size_t)(m0 + a_row1) * 256 + k0 + a_col1);
            int c0 = k0 + b_kr0, c1 = k0 + b_kr1;
            const float* s0 = (c0 < 128) ? (rb + (size_t)c0 * NPIX + n0 + b_nc0)
                                         : (ib + (size_t)(c0 - 128) * NPIX + n0 + b_nc0);
            const float* s1 = (c1 < 128) ? (rb + (size_t)c1 * NPIX + n0 + b_nc1)
                                         : (ib + (size_t)(c1 - 128) * NPIX + n0 + b_nc1);
            pb0 = *(const float4*)s0;
            pb1 = *(const float4*)s1;
        }

        // ---- compute 16 kk with packed FMAs ----
        #pragma unroll
        for (int kk = 0; kk < 16; kk++) {
            float4 a0 = *(const float4*)&As[kk][tm];
            float4 a1 = *(const float4*)&As[kk][tm + 4];
            const ull* bp = (const ull*)&Bs[kk][tn];
            ull bb[4];
            bb[0] = bp[0]; bb[1] = bp[1]; bb[2] = bp[2]; bb[3] = bp[3];
            float av[8] = {a0.x, a0.y, a0.z, a0.w, a1.x, a1.y, a1.z, a1.w};
            #pragma unroll
            for (int i = 0; i < 8; i++) {
                ull a2 = pack_dup(av[i]);
                #pragma unroll
                for (int j = 0; j < 4; j++) fma2(acc[i][j], a2, bb[j]);
            }
        }
        __syncthreads();

        if (kt < 15) {
            As[a_col0 + 0][a_row0] = pa0.x; As[a_col0 + 1][a_row0] = pa0.y;
            As[a_col0 + 2][a_row0] = pa0.z; As[a_col0 + 3][a_row0] = pa0.w;
            As[a_col1 + 0][a_row1] = pa1.x; As[a_col1 + 1][a_row1] = pa1.y;
            As[a_col1 + 2][a_row1] = pa1.z; As[a_col1 + 3][a_row1] = pa1.w;
            *(float4*)&Bs[b_kr0][b_nc0] = pb0;
            *(float4*)&Bs[b_kr1][b_nc1] = pb1;
            __syncthreads();
        }
    }

    float* outb = g_qkv + (size_t)b * 768 * NPIX;
    #pragma unroll
    for (int i = 0; i < 8; i++) {
        float v[8];
        #pragma unroll
        for (int j = 0; j < 4; j++) unpack2(v[2 * j], v[2 * j + 1], acc[i][j]);
        float* dst = outb + (size_t)(m0 + tm + i) * NPIX + n0 + tn;
        *(float4*)(dst)     = make_float4(v[0], v[1], v[2], v[3]);
        *(float4*)(dst + 4) = make_float4(v[4], v[5], v[6], v[7]);
    }
}

// ---------------------------------------------------------------------------
// Kernel B: dilated local attention (channel-major). One thread per
// (b, dil, head, pixel). OOB neighbors give exact logit 0 (matches jnp.pad).
// ---------------------------------------------------------------------------
__global__ __launch_bounds__(256) void attn_kernel()
{
    const int n    = blockIdx.x * 256 + threadIdx.x;
    const int dh   = blockIdx.y;
    const int dil  = dh >> 2;
    const int head = dh & 3;
    const int b    = blockIdx.z;
    const int d    = dil ? 3 : 2;

    const int r = n / 80;
    const int c = n % 80;

    const float* qb = g_qkv + ((size_t)(b * 768 + dil * 128 + head * 32)) * NPIX + n;
    const float* kb = qb + (size_t)256 * NPIX;
    const float* vb = qb + (size_t)512 * NPIX;

    float q[32];
    #pragma unroll
    for (int hd = 0; hd < 32; hd++) q[hd] = qb[hd * NPIX];

    float sc[9];
    #pragma unroll
    for (int jj = 0; jj < 9; jj++) {
        int di = jj / 3 - 1, dj = jj % 3 - 1;
        int rr = r + di * d, cc = c + dj * d;
        float s = 0.f;
        if (rr >= 0 && rr < 80 && cc >= 0 && cc < 80) {
            int off = di * d * 80 + dj * d;
            #pragma unroll
            for (int hd = 0; hd < 32; hd++)
                s = fmaf(q[hd], kb[hd * NPIX + off], s);
        }
        sc[jj] = s * SCALE;
    }

    float m = sc[0];
    #pragma unroll
    for (int jj = 1; jj < 9; jj++) m = fmaxf(m, sc[jj]);
    float sum = 0.f;
    #pragma unroll
    for (int jj = 0; jj < 9; jj++) { sc[jj] = __expf(sc[jj] - m); sum += sc[jj]; }
    const float inv = 1.f / sum;

    float out[32];
    #pragma unroll
    for (int hd = 0; hd < 32; hd++) out[hd] = 0.f;

    #pragma unroll
    for (int jj = 0; jj < 9; jj++) {
        int di = jj / 3 - 1, dj = jj % 3 - 1;
        int rr = r + di * d, cc = c + dj * d;
        if (rr >= 0 && rr < 80 && cc >= 0 && cc < 80) {
            int off = di * d * 80 + dj * d;
            float p = sc[jj] * inv;
            #pragma unroll
            for (int hd = 0; hd < 32; hd++)
                out[hd] = fmaf(p, vb[hd * NPIX + off], out[hd]);
        }
    }

    float* ob = g_attn + ((size_t)(b * 256 + dil * 128 + head * 32)) * NPIX + n;
    #pragma unroll
    for (int hd = 0; hd < 32; hd++) ob[hd * NPIX] = out[hd];
}

// ---------------------------------------------------------------------------
// Kernel C: out[b][n][o] = sum_c w_proj[o][c]*attn[b][c][n] + b_proj[o] + resid
// Same FFMA2 GEMM; epilogue adds bias + residual, writes [b][n][o].
// ---------------------------------------------------------------------------
__global__ __launch_bounds__(256) void proj_kernel(const float* __restrict__ w,
                                                   const float* __restrict__ bias,
                                                   const float* __restrict__ rgb,
                                                   const float* __restrict__ ir,
                                                   float* __restrict__ out)
{
    __shared__ float As[16][128];
    __shared__ float Bs[16][128];

    const int b  = blockIdx.z;
    const int n0 = blockIdx.x * 128;
    const int m0 = blockIdx.y * 128;
    const int tid = threadIdx.x;
    const int tm = (tid >> 4) * 8;
    const int tn = (tid & 15) * 8;

    const float* ab = g_attn + (size_t)b * 256 * NPIX;

    const int a_row0 = (tid * 2) >> 2,      a_col0 = ((tid * 2) & 3) * 4;
    const int a_row1 = (tid * 2 + 1) >> 2,  a_col1 = ((tid * 2 + 1) & 3) * 4;
    const int b_kr0 = (tid * 2) >> 5,       b_nc0 = ((tid * 2) & 31) * 4;
    const int b_kr1 = (tid * 2 + 1) >> 5,   b_nc1 = ((tid * 2 + 1) & 31) * 4;

    ull acc[8][4];
    #pragma unroll
    for (int i = 0; i < 8; i++)
        #pragma unroll
        for (int j = 0; j < 4; j++) acc[i][j] = 0ull;

    {
        float4 va0 = *(const float4*)(w + (size_t)(m0 + a_row0) * 256 + a_col0);
        float4 va1 = *(const float4*)(w + (size_t)(m0 + a_row1) * 256 + a_col1);
        As[a_col0 + 0][a_row0] = va0.x; As[a_col0 + 1][a_row0] = va0.y;
        As[a_col0 + 2][a_row0] = va0.z; As[a_col0 + 3][a_row0] = va0.w;
        As[a_col1 + 0][a_row1] = va1.x; As[a_col1 + 1][a_row1] = va1.y;
        As[a_col1 + 2][a_row1] = va1.z; As[a_col1 + 3][a_row1] = va1.w;
        *(float4*)&Bs[b_kr0][b_nc0] = *(const float4*)(ab + (size_t)b_kr0 * NPIX + n0 + b_nc0);
        *(float4*)&Bs[b_kr1][b_nc1] = *(const float4*)(ab + (size_t)b_kr1 * NPIX + n0 + b_nc1);
    }
    __syncthreads();

    for (int kt = 0; kt < 16; kt++) {
        float4 pa0, pa1, pb0, pb1;
        if (kt < 15) {
            const int k0 = (kt + 1) * 16;
            pa0 = *(const float4*)(w + (size_t)(m0 + a_row0) * 256 + k0 + a_col0);
            pa1 = *(const float4*)(w + (size_t)(m0 + a_row1) * 256 + k0 + a_col1);
            pb0 = *(const float4*)(ab + (size_t)(k0 + b_kr0) * NPIX + n0 + b_nc0);
            pb1 = *(const float4*)(ab + (size_t)(k0 + b_kr1) * NPIX + n0 + b_nc1);
        }

        #pragma unroll
        for (int kk = 0; kk < 16; kk++) {
            float4 a0 = *(const float4*)&As[kk][tm];
            float4 a1 = *(const float4*)&As[kk][tm + 4];
            const ull* bp = (const ull*)&Bs[kk][tn];
            ull bb[4];
            bb[0] = bp[0]; bb[1] = bp[1]; bb[2] = bp[2]; bb[3] = bp[3];
            float av[8] = {a0.x, a0.y, a0.z, a0.w, a1.x, a1.y, a1.z, a1.w};
            #pragma unroll
            for (int i = 0; i < 8; i++) {
                ull a2 = pack_dup(av[i]);
                #pragma unroll
                for (int j = 0; j < 4; j++) fma2(acc[i][j], a2, bb[j]);
            }
        }
        __syncthreads();

        if (kt < 15) {
            As[a_col0 + 0][a_row0] = pa0.x; As[a_col0 + 1][a_row0] = pa0.y;
            As[a_col0 + 2][a_row0] = pa0.z; As[a_col0 + 3][a_row0] = pa0.w;
            As[a_col1 + 0][a_row1] = pa1.x; As[a_col1 + 1][a_row1] = pa1.y;
            As[a_col1 + 2][a_row1] = pa1.z; As[a_col1 + 3][a_row1] = pa1.w;
            *(float4*)&Bs[b_kr0][b_nc0] = pb0;
            *(float4*)&Bs[b_kr1][b_nc1] = pb1;
            __syncthreads();
        }
    }

    // Epilogue: bias + residual, write [b, n, o]
    float bp[8];
    #pragma unroll
    for (int i = 0; i < 8; i++) bp[i] = bias[m0 + tm + i];

    const float* resb = ((m0 == 0) ? rgb : ir) + (size_t)b * 128 * NPIX;

    float vr[8][8];
    #pragma unroll
    for (int i = 0; i < 8; i++)
        #pragma unroll
        for (int j = 0; j < 4; j++) unpack2(vr[i][2 * j], vr[i][2 * j + 1], acc[i][j]);

    #pragma unroll
    for (int j = 0; j < 8; j++) {
        int n = n0 + tn + j;
        float v[8];
        #pragma unroll
        for (int i = 0; i < 8; i++) {
            float res = resb[(size_t)(tm + i) * NPIX + n];
            v[i] = vr[i][j] + bp[i] + res;
        }
        float* dst = out + ((size_t)(b * NPIX + n)) * 256 + m0 + tm;
        *(float4*)(dst)     = make_float4(v[0], v[1], v[2], v[3]);
        *(float4*)(dst + 4) = make_float4(v[4], v[5], v[6], v[7]);
    }
}

// ---------------------------------------------------------------------------
extern "C" void kernel_launch(void* const* d_in, const int* in_sizes, int n_in,
                              void* d_out, int out_size)
{
    const float* rgb    = (const float*)d_in[0];
    const float* ir     = (const float*)d_in[1];
    const float* w_qkv  = (const float*)d_in[2];
    const float* w_proj = (const float*)d_in[3];
    const float* b_proj = (const float*)d_in[4];
    float* out = (float*)d_out;

    qkv_gemm<<<dim3(50, 6, 4), 256>>>(rgb, ir, w_qkv);
    attn_kernel<<<dim3(25, 8, 4), 256>>>();
    proj_kernel<<<dim3(50, 2, 4), 256>>>(w_proj, b_proj, rgb, ir, out);
}

// round 4
// speedup vs baseline: 2.5371x; 2.5371x over previous
#include <cuda_runtime.h>
#include <cstdint>

#define NPIX   6400
#define SCALE  0.17677669529663687f   // 32^-0.5

// Scratch (device globals), channel-major layouts
__device__ float g_qkv [4 * 768 * 6400];   // [b][o][n]
__device__ float g_attn[4 * 256 * 6400];   // [b][ch][n]

// ---------------------------------------------------------------------------
// Helpers (sm_80-class PTX only: family-safe on compute_103)
// ---------------------------------------------------------------------------
__device__ __forceinline__ uint32_t smem_u32(const void* p) {
    uint32_t a;
    asm("{ .reg .u64 t; cvta.to.shared.u64 t, %1; cvt.u32.u64 %0, t; }" : "=r"(a) : "l"(p));
    return a;
}
__device__ __forceinline__ void cp16(uint32_t dst, const void* src) {
    asm volatile("cp.async.cg.shared.global [%0], [%1], 16;" :: "r"(dst), "l"(src));
}
#define CP_COMMIT() asm volatile("cp.async.commit_group;" ::: "memory")
#define CP_WAIT1()  asm volatile("cp.async.wait_group 1;" ::: "memory")

__device__ __forceinline__ uint32_t f2tf32(float x) {
    uint32_t u;
    asm("cvt.rna.tf32.f32 %0, %1;" : "=r"(u) : "f"(x));
    return u;
}
__device__ __forceinline__ void mma_tf32(float c[4],
                                         uint32_t a0, uint32_t a1, uint32_t a2, uint32_t a3,
                                         uint32_t b0, uint32_t b1) {
    asm volatile("mma.sync.aligned.m16n8k8.row.col.f32.tf32.tf32.f32 "
                 "{%0,%1,%2,%3}, {%4,%5,%6,%7}, {%8,%9}, {%0,%1,%2,%3};"
                 : "+f"(c[0]), "+f"(c[1]), "+f"(c[2]), "+f"(c[3])
                 : "r"(a0), "r"(a1), "r"(a2), "r"(a3), "r"(b0), "r"(b1));
}

// Smem layout (per stage): A [128 m][20] floats (16 k + pad), B [16 k][136] floats
#define AS_STRIDE 20
#define AS_SIZE   (128 * AS_STRIDE)      // 2560
#define BS_STRIDE 136
#define BS_SIZE   (16 * BS_STRIDE)       // 2176
#define STAGE_F   (AS_SIZE + BS_SIZE)    // 4736 floats

// ---------------------------------------------------------------------------
// Shared GEMM compute: one k-tile (16 k) of warp-tiled m16n8k8 tf32 MMAs.
// Warp grid 2(m) x 4(n); warp tile 64 x 32.
// ---------------------------------------------------------------------------
__device__ __forceinline__ void gemm_ktile(const float* As, const float* Bs,
                                           int wm0, int wn0, int row, int colk,
                                           float acc[4][4][4]) {
    #pragma unroll
    for (int ks = 0; ks < 2; ks++) {
        const int kb = ks * 8;
        uint32_t a[4][4], bfr[4][2];
        #pragma unroll
        for (int mt = 0; mt < 4; mt++) {
            const float* ab = As + (wm0 + mt * 16 + row) * AS_STRIDE + kb + colk;
            a[mt][0] = f2tf32(ab[0]);
            a[mt][1] = f2tf32(ab[8 * AS_STRIDE]);
            a[mt][2] = f2tf32(ab[4]);
            a[mt][3] = f2tf32(ab[8 * AS_STRIDE + 4]);
        }
        #pragma unroll
        for (int nt = 0; nt < 4; nt++) {
            const float* bb = Bs + (kb + colk) * BS_STRIDE + wn0 + nt * 8 + row;
            bfr[nt][0] = f2tf32(bb[0]);
            bfr[nt][1] = f2tf32(bb[4 * BS_STRIDE]);
        }
        #pragma unroll
        for (int mt = 0; mt < 4; mt++)
            #pragma unroll
            for (int nt = 0; nt < 4; nt++)
                mma_tf32(acc[mt][nt], a[mt][0], a[mt][1], a[mt][2], a[mt][3],
                         bfr[nt][0], bfr[nt][1]);
    }
}

// ---------------------------------------------------------------------------
// Kernel A: qkv[b][o][n] = sum_c w_qkv[o][c] * y[b][c][n]
// ---------------------------------------------------------------------------
__global__ __launch_bounds__(256, 2) void qkv_gemm(const float* __restrict__ rgb,
                                                   const float* __restrict__ ir,
                                                   const float* __restrict__ w)
{
    __shared__ __align__(16) float buf[2 * STAGE_F];

    const int b  = blockIdx.z;
    const int n0 = blockIdx.x * 128;
    const int m0 = blockIdx.y * 128;
    const int tid = threadIdx.x;
    const int wid = tid >> 5, lane = tid & 31;
    const int wm0 = (wid >> 2) * 64, wn0 = (wid & 3) * 32;
    const int row = lane >> 2, colk = lane & 3;

    const float* rb = rgb + (size_t)b * 128 * NPIX;
    const float* ib = ir  + (size_t)b * 128 * NPIX;

    // Per-thread cp.async coordinates (2 chunks each for A and B)
    const int am0 = (tid) >> 2,        akc0 = (tid) & 3;
    const int am1 = (tid + 256) >> 2,  akc1 = (tid + 256) & 3;
    const int bk0 = (tid) >> 5,        bnc0 = (tid) & 31;
    const int bk1 = (tid + 256) >> 5,  bnc1 = (tid + 256) & 31;

    const uint32_t sbase = smem_u32(buf);

    auto load_tile = [&](int kt, int stage) {
        const int k0 = kt * 16;
        const uint32_t As = sbase + stage * STAGE_F * 4;
        const uint32_t Bs = As + AS_SIZE * 4;
        cp16(As + (am0 * AS_STRIDE + akc0 * 4) * 4, w + (size_t)(m0 + am0) * 256 + k0 + akc0 * 4);
        cp16(As + (am1 * AS_STRIDE + akc1 * 4) * 4, w + (size_t)(m0 + am1) * 256 + k0 + akc1 * 4);
        int c0 = k0 + bk0, c1 = k0 + bk1;
        const float* s0 = (c0 < 128) ? (rb + (size_t)c0 * NPIX) : (ib + (size_t)(c0 - 128) * NPIX);
        const float* s1 = (c1 < 128) ? (rb + (size_t)c1 * NPIX) : (ib + (size_t)(c1 - 128) * NPIX);
        cp16(Bs + (bk0 * BS_STRIDE + bnc0 * 4) * 4, s0 + n0 + bnc0 * 4);
        cp16(Bs + (bk1 * BS_STRIDE + bnc1 * 4) * 4, s1 + n0 + bnc1 * 4);
    };

    float acc[4][4][4];
    #pragma unroll
    for (int mt = 0; mt < 4; mt++)
        #pragma unroll
        for (int nt = 0; nt < 4; nt++)
            #pragma unroll
            for (int i = 0; i < 4; i++) acc[mt][nt][i] = 0.f;

    load_tile(0, 0); CP_COMMIT();
    load_tile(1, 1); CP_COMMIT();

    for (int kt = 0; kt < 16; kt++) {
        CP_WAIT1();
        __syncthreads();
        const float* As = buf + (kt & 1) * STAGE_F;
        const float* Bs = As + AS_SIZE;
        gemm_ktile(As, Bs, wm0, wn0, row, colk, acc);
        __syncthreads();
        if (kt + 2 < 16) load_tile(kt + 2, kt & 1);
        CP_COMMIT();
    }

    // Epilogue: write [b][o][n], float2 per (c0,c1)/(c2,c3)
    float* outb = g_qkv + (size_t)b * 768 * NPIX;
    #pragma unroll
    for (int mt = 0; mt < 4; mt++) {
        #pragma unroll
        for (int nt = 0; nt < 4; nt++) {
            int o = m0 + wm0 + mt * 16 + row;
            int n = n0 + wn0 + nt * 8 + 2 * colk;
            *(float2*)(outb + (size_t)o * NPIX + n) =
                make_float2(acc[mt][nt][0], acc[mt][nt][1]);
            *(float2*)(outb + (size_t)(o + 8) * NPIX + n) =
                make_float2(acc[mt][nt][2], acc[mt][nt][3]);
        }
    }
}

// ---------------------------------------------------------------------------
// Kernel B: dilated local attention (channel-major), 1 thread per (b,dil,head,pix)
// ---------------------------------------------------------------------------
__global__ __launch_bounds__(256) void attn_kernel()
{
    const int n    = blockIdx.x * 256 + threadIdx.x;
    const int dh   = blockIdx.y;
    const int dil  = dh >> 2;
    const int head = dh & 3;
    const int b    = blockIdx.z;
    const int d    = dil ? 3 : 2;

    const int r = n / 80;
    const int c = n % 80;

    const float* qb = g_qkv + ((size_t)(b * 768 + dil * 128 + head * 32)) * NPIX + n;
    const float* kb = qb + (size_t)256 * NPIX;
    const float* vb = qb + (size_t)512 * NPIX;

    float q[32];
    #pragma unroll
    for (int hd = 0; hd < 32; hd++) q[hd] = qb[hd * NPIX];

    float sc[9];
    #pragma unroll
    for (int jj = 0; jj < 9; jj++) {
        int di = jj / 3 - 1, dj = jj % 3 - 1;
        int rr = r + di * d, cc = c + dj * d;
        float s = 0.f;
        if (rr >= 0 && rr < 80 && cc >= 0 && cc < 80) {
            int off = di * d * 80 + dj * d;
            #pragma unroll
            for (int hd = 0; hd < 32; hd++)
                s = fmaf(q[hd], kb[hd * NPIX + off], s);
        }
        sc[jj] = s * SCALE;
    }

    float m = sc[0];
    #pragma unroll
    for (int jj = 1; jj < 9; jj++) m = fmaxf(m, sc[jj]);
    float sum = 0.f;
    #pragma unroll
    for (int jj = 0; jj < 9; jj++) { sc[jj] = __expf(sc[jj] - m); sum += sc[jj]; }
    const float inv = 1.f / sum;

    float out[32];
    #pragma unroll
    for (int hd = 0; hd < 32; hd++) out[hd] = 0.f;

    #pragma unroll
    for (int jj = 0; jj < 9; jj++) {
        int di = jj / 3 - 1, dj = jj % 3 - 1;
        int rr = r + di * d, cc = c + dj * d;
        if (rr >= 0 && rr < 80 && cc >= 0 && cc < 80) {
            int off = di * d * 80 + dj * d;
            float p = sc[jj] * inv;
            #pragma unroll
            for (int hd = 0; hd < 32; hd++)
                out[hd] = fmaf(p, vb[hd * NPIX + off], out[hd]);
        }
    }

    float* ob = g_attn + ((size_t)(b * 256 + dil * 128 + head * 32)) * NPIX + n;
    #pragma unroll
    for (int hd = 0; hd < 32; hd++) ob[hd * NPIX] = out[hd];
}

// ---------------------------------------------------------------------------
// Kernel C: out[b][n][o] = sum_c w_proj[o][c]*attn[b][c][n] + b_proj[o] + resid
// ---------------------------------------------------------------------------
__global__ __launch_bounds__(256, 2) void proj_kernel(const float* __restrict__ w,
                                                      const float* __restrict__ bias,
                                                      const float* __restrict__ rgb,
                                                      const float* __restrict__ ir,
                                                      float* __restrict__ out)
{
    __shared__ __align__(16) float buf[2 * STAGE_F];

    const int b  = blockIdx.z;
    const int n0 = blockIdx.x * 128;
    const int m0 = blockIdx.y * 128;
    const int tid = threadIdx.x;
    const int wid = tid >> 5, lane = tid & 31;
    const int wm0 = (wid >> 2) * 64, wn0 = (wid & 3) * 32;
    const int row = lane >> 2, colk = lane & 3;

    const float* ab = g_attn + (size_t)b * 256 * NPIX;

    const int am0 = (tid) >> 2,        akc0 = (tid) & 3;
    const int am1 = (tid + 256) >> 2,  akc1 = (tid + 256) & 3;
    const int bk0 = (tid) >> 5,        bnc0 = (tid) & 31;
    const int bk1 = (tid + 256) >> 5,  bnc1 = (tid + 256) & 31;

    const uint32_t sbase = smem_u32(buf);

    auto load_tile = [&](int kt, int stage) {
        const int k0 = kt * 16;
        const uint32_t As = sbase + stage * STAGE_F * 4;
        const uint32_t Bs = As + AS_SIZE * 4;
        cp16(As + (am0 * AS_STRIDE + akc0 * 4) * 4, w + (size_t)(m0 + am0) * 256 + k0 + akc0 * 4);
        cp16(As + (am1 * AS_STRIDE + akc1 * 4) * 4, w + (size_t)(m0 + am1) * 256 + k0 + akc1 * 4);
        cp16(Bs + (bk0 * BS_STRIDE + bnc0 * 4) * 4, ab + (size_t)(k0 + bk0) * NPIX + n0 + bnc0 * 4);
        cp16(Bs + (bk1 * BS_STRIDE + bnc1 * 4) * 4, ab + (size_t)(k0 + bk1) * NPIX + n0 + bnc1 * 4);
    };

    float acc[4][4][4];
    #pragma unroll
    for (int mt = 0; mt < 4; mt++)
        #pragma unroll
        for (int nt = 0; nt < 4; nt++)
            #pragma unroll
            for (int i = 0; i < 4; i++) acc[mt][nt][i] = 0.f;

    load_tile(0, 0); CP_COMMIT();
    load_tile(1, 1); CP_COMMIT();

    for (int kt = 0; kt < 16; kt++) {
        CP_WAIT1();
        __syncthreads();
        const float* As = buf + (kt & 1) * STAGE_F;
        const float* Bs = As + AS_SIZE;
        gemm_ktile(As, Bs, wm0, wn0, row, colk, acc);
        __syncthreads();
        if (kt + 2 < 16) load_tile(kt + 2, kt & 1);
        CP_COMMIT();
    }

    // Epilogue: + bias + residual, write out[b][n][o] (o contiguous)
    const float* resb = ((m0 == 0) ? rgb : ir) + (size_t)b * 128 * NPIX;
    float* outb = out + (size_t)b * NPIX * 256;

    #pragma unroll
    for (int mt = 0; mt < 4; mt++) {
        const int o_lo = m0 + wm0 + mt * 16 + row;
        const int o_hi = o_lo + 8;
        const float bias_lo = __ldg(bias + o_lo);
        const float bias_hi = __ldg(bias + o_hi);
        const float* res_lo = resb + (size_t)(o_lo & 127) * NPIX;
        const float* res_hi = resb + (size_t)(o_hi & 127) * NPIX;
        #pragma unroll
        for (int nt = 0; nt < 4; nt++) {
            const int n = n0 + wn0 + nt * 8 + 2 * colk;
            outb[(size_t)n * 256 + o_lo]       = acc[mt][nt][0] + bias_lo + res_lo[n];
            outb[(size_t)(n + 1) * 256 + o_lo] = acc[mt][nt][1] + bias_lo + res_lo[n + 1];
            outb[(size_t)n * 256 + o_hi]       = acc[mt][nt][2] + bias_hi + res_hi[n];
            outb[(size_t)(n + 1) * 256 + o_hi] = acc[mt][nt][3] + bias_hi + res_hi[n + 1];
        }
    }
}

// ---------------------------------------------------------------------------
extern "C" void kernel_launch(void* const* d_in, const int* in_sizes, int n_in,
                              void* d_out, int out_size)
{
    const float* rgb    = (const float*)d_in[0];
    const float* ir     = (const float*)d_in[1];
    const float* w_qkv  = (const float*)d_in[2];
    const float* w_proj = (const float*)d_in[3];
    const float* b_proj = (const float*)d_in[4];
    float* out = (float*)d_out;

    qkv_gemm<<<dim3(50, 6, 4), 256>>>(rgb, ir, w_qkv);
    attn_kernel<<<dim3(25, 8, 4), 256>>>();
    proj_kernel<<<dim3(50, 2, 4), 256>>>(w_proj, b_proj, rgb, ir, out);
}

// round 5
// speedup vs baseline: 2.6113x; 1.0293x over previous
#include <cuda_runtime.h>
#include <cstdint>

#define NPIX   6400
#define SCALE  0.17677669529663687f   // 32^-0.5

// Scratch (device globals), channel-major layouts
__device__ float g_qkv [4 * 768 * 6400];   // [b][o][n]  fp32 (MMA output)
__device__ float g_attn[4 * 256 * 6400];   // [b][ch][n] tf32-rounded bits
__device__ float g_ytf [4 * 256 * 6400];   // [b][c][n]  tf32-rounded y
__device__ float g_wq  [768 * 256];        // w_qkv, tf32-rounded, k-interleaved
__device__ float g_wp  [256 * 256];        // w_proj, tf32-rounded, k-interleaved

// ---------------------------------------------------------------------------
// Helpers (sm_80-class PTX only: family-safe on compute_103)
// ---------------------------------------------------------------------------
__device__ __forceinline__ uint32_t smem_u32(const void* p) {
    uint32_t a;
    asm("{ .reg .u64 t; cvta.to.shared.u64 t, %1; cvt.u32.u64 %0, t; }" : "=r"(a) : "l"(p));
    return a;
}
__device__ __forceinline__ void cp16(uint32_t dst, const void* src) {
    asm volatile("cp.async.cg.shared.global [%0], [%1], 16;" :: "r"(dst), "l"(src));
}
#define CP_COMMIT() asm volatile("cp.async.commit_group;" ::: "memory")
#define CP_WAIT1()  asm volatile("cp.async.wait_group 1;" ::: "memory")

__device__ __forceinline__ uint32_t f2tf32(float x) {
    uint32_t u;
    asm("cvt.rna.tf32.f32 %0, %1;" : "=r"(u) : "f"(x));
    return u;
}
__device__ __forceinline__ void mma_tf32(float c[4],
                                         uint32_t a0, uint32_t a1, uint32_t a2, uint32_t a3,
                                         uint32_t b0, uint32_t b1) {
    asm volatile("mma.sync.aligned.m16n8k8.row.col.f32.tf32.tf32.f32 "
                 "{%0,%1,%2,%3}, {%4,%5,%6,%7}, {%8,%9}, {%0,%1,%2,%3};"
                 : "+f"(c[0]), "+f"(c[1]), "+f"(c[2]), "+f"(c[3])
                 : "r"(a0), "r"(a1), "r"(a2), "r"(a3), "r"(b0), "r"(b1));
}

// Smem layout (per stage): A [128 m][24] floats (16 k interleaved + pad),
//                          B [16 k][136] floats
#define AS_STRIDE 24
#define AS_SIZE   (128 * AS_STRIDE)      // 3072 floats
#define BS_STRIDE 136
#define BS_SIZE   (16 * BS_STRIDE)       // 2176 floats
#define STAGE_F   (AS_SIZE + BS_SIZE)    // 5248 floats (20.5KB) x2 = 41KB

// ---------------------------------------------------------------------------
// Conversion prologue kernels
// ---------------------------------------------------------------------------
// y = concat(rgb, ir) -> g_ytf, tf32-rounded, float4 per thread
__global__ __launch_bounds__(256) void conv_y(const float* __restrict__ rgb,
                                              const float* __restrict__ ir)
{
    const size_t idx = ((size_t)blockIdx.x * 256 + threadIdx.x) * 4;  // float index
    const size_t half = (size_t)4 * 128 * NPIX;                        // rgb total
    // global c-major: [b][c][n]; map linear over both halves
    const size_t bcn = idx;                        // within [b][c][n] with c<128 -> rgb
    const size_t b   = bcn / (256 * (size_t)NPIX);
    const size_t rem = bcn % (256 * (size_t)NPIX);
    const float* src = (rem < 128 * (size_t)NPIX)
        ? rgb + b * 128 * NPIX + rem
        : ir  + b * 128 * NPIX + (rem - 128 * (size_t)NPIX);
    float4 v = *(const float4*)src;
    float4 o;
    o.x = __uint_as_float(f2tf32(v.x));
    o.y = __uint_as_float(f2tf32(v.y));
    o.z = __uint_as_float(f2tf32(v.z));
    o.w = __uint_as_float(f2tf32(v.w));
    *(float4*)(g_ytf + idx) = o;
    (void)half;
}

// weights -> tf32-rounded + k-interleaved within each 8-block:
// dst[o][ (k & ~7) | (((k&3)<<1)|(k>>2 & 1)) ] = tf32(src[o][k])
__global__ __launch_bounds__(256) void conv_w(const float* __restrict__ wq,
                                              const float* __restrict__ wp)
{
    const int row = blockIdx.x;          // 0..1023 : 0..767 wq, 768..1023 wp
    const int k   = threadIdx.x;         // 0..255
    const int kp  = (k & ~7) | (((k & 3) << 1) | ((k >> 2) & 1));
    if (row < 768) {
        g_wq[row * 256 + kp] = __uint_as_float(f2tf32(wq[row * 256 + k]));
    } else {
        int r = row - 768;
        g_wp[r * 256 + kp] = __uint_as_float(f2tf32(wp[r * 256 + k]));
    }
}

// ---------------------------------------------------------------------------
// Shared GEMM compute: one k-tile (16 k) of warp-tiled m16n8k8 tf32 MMAs.
// Warp grid 2(m) x 4(n); warp tile 64 x 32. No cvt: smem holds tf32 bits.
// ---------------------------------------------------------------------------
__device__ __forceinline__ void gemm_ktile(const float* As, const float* Bs,
                                           int wm0, int wn0, int row, int colk,
                                           float acc[4][4][4]) {
    #pragma unroll
    for (int ks = 0; ks < 2; ks++) {
        const int kb = ks * 8;
        uint32_t a[4][4], bfr[4][2];
        #pragma unroll
        for (int mt = 0; mt < 4; mt++) {
            const float* ab = As + (wm0 + mt * 16 + row) * AS_STRIDE + kb + 2 * colk;
            float2 lo = *(const float2*)ab;                    // k=colk, k=colk+4
            float2 hi = *(const float2*)(ab + 8 * AS_STRIDE);  // row+8
            a[mt][0] = __float_as_uint(lo.x);
            a[mt][1] = __float_as_uint(hi.x);
            a[mt][2] = __float_as_uint(lo.y);
            a[mt][3] = __float_as_uint(hi.y);
        }
        #pragma unroll
        for (int nt = 0; nt < 4; nt++) {
            const float* bb = Bs + (kb + colk) * BS_STRIDE + wn0 + nt * 8 + row;
            bfr[nt][0] = __float_as_uint(bb[0]);
            bfr[nt][1] = __float_as_uint(bb[4 * BS_STRIDE]);
        }
        #pragma unroll
        for (int mt = 0; mt < 4; mt++)
            #pragma unroll
            for (int nt = 0; nt < 4; nt++)
                mma_tf32(acc[mt][nt], a[mt][0], a[mt][1], a[mt][2], a[mt][3],
                         bfr[nt][0], bfr[nt][1]);
    }
}

// ---------------------------------------------------------------------------
// Kernel A: qkv[b][o][n] = sum_c w_qkv[o][c] * y[b][c][n]
// ---------------------------------------------------------------------------
__global__ __launch_bounds__(256, 2) void qkv_gemm()
{
    __shared__ __align__(16) float buf[2 * STAGE_F];

    const int b  = blockIdx.z;
    const int n0 = blockIdx.x * 128;
    const int m0 = blockIdx.y * 128;
    const int tid = threadIdx.x;
    const int wid = tid >> 5, lane = tid & 31;
    const int wm0 = (wid >> 2) * 64, wn0 = (wid & 3) * 32;
    const int row = lane >> 2, colk = lane & 3;

    const float* yb = g_ytf + (size_t)b * 256 * NPIX;

    const int am0 = (tid) >> 2,        akc0 = (tid) & 3;
    const int am1 = (tid + 256) >> 2,  akc1 = (tid + 256) & 3;
    const int bk0 = (tid) >> 5,        bnc0 = (tid) & 31;
    const int bk1 = (tid + 256) >> 5,  bnc1 = (tid + 256) & 31;

    const uint32_t sbase = smem_u32(buf);

    auto load_tile = [&](int kt, int stage) {
        const int k0 = kt * 16;
        const uint32_t As = sbase + stage * STAGE_F * 4;
        const uint32_t Bs = As + AS_SIZE * 4;
        cp16(As + (am0 * AS_STRIDE + akc0 * 4) * 4, g_wq + (size_t)(m0 + am0) * 256 + k0 + akc0 * 4);
        cp16(As + (am1 * AS_STRIDE + akc1 * 4) * 4, g_wq + (size_t)(m0 + am1) * 256 + k0 + akc1 * 4);
        cp16(Bs + (bk0 * BS_STRIDE + bnc0 * 4) * 4, yb + (size_t)(k0 + bk0) * NPIX + n0 + bnc0 * 4);
        cp16(Bs + (bk1 * BS_STRIDE + bnc1 * 4) * 4, yb + (size_t)(k0 + bk1) * NPIX + n0 + bnc1 * 4);
    };

    float acc[4][4][4];
    #pragma unroll
    for (int mt = 0; mt < 4; mt++)
        #pragma unroll
        for (int nt = 0; nt < 4; nt++)
            #pragma unroll
            for (int i = 0; i < 4; i++) acc[mt][nt][i] = 0.f;

    load_tile(0, 0); CP_COMMIT();
    load_tile(1, 1); CP_COMMIT();

    for (int kt = 0; kt < 16; kt++) {
        CP_WAIT1();
        __syncthreads();
        const float* As = buf + (kt & 1) * STAGE_F;
        const float* Bs = As + AS_SIZE;
        gemm_ktile(As, Bs, wm0, wn0, row, colk, acc);
        __syncthreads();
        if (kt + 2 < 16) load_tile(kt + 2, kt & 1);
        CP_COMMIT();
    }

    float* outb = g_qkv + (size_t)b * 768 * NPIX;
    #pragma unroll
    for (int mt = 0; mt < 4; mt++) {
        #pragma unroll
        for (int nt = 0; nt < 4; nt++) {
            int o = m0 + wm0 + mt * 16 + row;
            int n = n0 + wn0 + nt * 8 + 2 * colk;
            *(float2*)(outb + (size_t)o * NPIX + n) =
                make_float2(acc[mt][nt][0], acc[mt][nt][1]);
            *(float2*)(outb + (size_t)(o + 8) * NPIX + n) =
                make_float2(acc[mt][nt][2], acc[mt][nt][3]);
        }
    }
}

// ---------------------------------------------------------------------------
// Kernel B: dilated local attention (channel-major), 1 thread per (b,dil,head,pix)
// Output written tf32-rounded (proj consumes raw bits).
// ---------------------------------------------------------------------------
__global__ __launch_bounds__(256) void attn_kernel()
{
    const int n    = blockIdx.x * 256 + threadIdx.x;
    const int dh   = blockIdx.y;
    const int dil  = dh >> 2;
    const int head = dh & 3;
    const int b    = blockIdx.z;
    const int d    = dil ? 3 : 2;

    const int r = n / 80;
    const int c = n % 80;

    const float* qb = g_qkv + ((size_t)(b * 768 + dil * 128 + head * 32)) * NPIX + n;
    const float* kb = qb + (size_t)256 * NPIX;
    const float* vb = qb + (size_t)512 * NPIX;

    float q[32];
    #pragma unroll
    for (int hd = 0; hd < 32; hd++) q[hd] = qb[hd * NPIX];

    float sc[9];
    #pragma unroll
    for (int jj = 0; jj < 9; jj++) {
        int di = jj / 3 - 1, dj = jj % 3 - 1;
        int rr = r + di * d, cc = c + dj * d;
        float s = 0.f;
        if (rr >= 0 && rr < 80 && cc >= 0 && cc < 80) {
            int off = di * d * 80 + dj * d;
            #pragma unroll
            for (int hd = 0; hd < 32; hd++)
                s = fmaf(q[hd], kb[hd * NPIX + off], s);
        }
        sc[jj] = s * SCALE;
    }

    float m = sc[0];
    #pragma unroll
    for (int jj = 1; jj < 9; jj++) m = fmaxf(m, sc[jj]);
    float sum = 0.f;
    #pragma unroll
    for (int jj = 0; jj < 9; jj++) { sc[jj] = __expf(sc[jj] - m); sum += sc[jj]; }
    const float inv = 1.f / sum;

    float out[32];
    #pragma unroll
    for (int hd = 0; hd < 32; hd++) out[hd] = 0.f;

    #pragma unroll
    for (int jj = 0; jj < 9; jj++) {
        int di = jj / 3 - 1, dj = jj % 3 - 1;
        int rr = r + di * d, cc = c + dj * d;
        if (rr >= 0 && rr < 80 && cc >= 0 && cc < 80) {
            int off = di * d * 80 + dj * d;
            float p = sc[jj] * inv;
            #pragma unroll
            for (int hd = 0; hd < 32; hd++)
                out[hd] = fmaf(p, vb[hd * NPIX + off], out[hd]);
        }
    }

    float* ob = g_attn + ((size_t)(b * 256 + dil * 128 + head * 32)) * NPIX + n;
    #pragma unroll
    for (int hd = 0; hd < 32; hd++)
        ob[hd * NPIX] = __uint_as_float(f2tf32(out[hd]));
}

// ---------------------------------------------------------------------------
// Kernel C: out[b][n][o] = sum_c w_proj[o][c]*attn[b][c][n] + b_proj[o] + resid
// ---------------------------------------------------------------------------
__global__ __launch_bounds__(256, 2) void proj_kernel(const float* __restrict__ bias,
                                                      const float* __restrict__ rgb,
                                                      const float* __restrict__ ir,
                                                      float* __restrict__ out)
{
    __shared__ __align__(16) float buf[2 * STAGE_F];

    const int b  = blockIdx.z;
    const int n0 = blockIdx.x * 128;
    const int m0 = blockIdx.y * 128;
    const int tid = threadIdx.x;
    const int wid = tid >> 5, lane = tid & 31;
    const int wm0 = (wid >> 2) * 64, wn0 = (wid & 3) * 32;
    const int row = lane >> 2, colk = lane & 3;

    const float* ab = g_attn + (size_t)b * 256 * NPIX;

    const int am0 = (tid) >> 2,        akc0 = (tid) & 3;
    const int am1 = (tid + 256) >> 2,  akc1 = (tid + 256) & 3;
    const int bk0 = (tid) >> 5,        bnc0 = (tid) & 31;
    const int bk1 = (tid + 256) >> 5,  bnc1 = (tid + 256) & 31;

    const uint32_t sbase = smem_u32(buf);

    auto load_tile = [&](int kt, int stage) {
        const int k0 = kt * 16;
        const uint32_t As = sbase + stage * STAGE_F * 4;
        const uint32_t Bs = As + AS_SIZE * 4;
        cp16(As + (am0 * AS_STRIDE + akc0 * 4) * 4, g_wp + (size_t)(m0 + am0) * 256 + k0 + akc0 * 4);
        cp16(As + (am1 * AS_STRIDE + akc1 * 4) * 4, g_wp + (size_t)(m0 + am1) * 256 + k0 + akc1 * 4);
        cp16(Bs + (bk0 * BS_STRIDE + bnc0 * 4) * 4, ab + (size_t)(k0 + bk0) * NPIX + n0 + bnc0 * 4);
        cp16(Bs + (bk1 * BS_STRIDE + bnc1 * 4) * 4, ab + (size_t)(k0 + bk1) * NPIX + n0 + bnc1 * 4);
    };

    float acc[4][4][4];
    #pragma unroll
    for (int mt = 0; mt < 4; mt++)
        #pragma unroll
        for (int nt = 0; nt < 4; nt++)
            #pragma unroll
            for (int i = 0; i < 4; i++) acc[mt][nt][i] = 0.f;

    load_tile(0, 0); CP_COMMIT();
    load_tile(1, 1); CP_COMMIT();

    for (int kt = 0; kt < 16; kt++) {
        CP_WAIT1();
        __syncthreads();
        const float* As = buf + (kt & 1) * STAGE_F;
        const float* Bs = As + AS_SIZE;
        gemm_ktile(As, Bs, wm0, wn0, row, colk, acc);
        __syncthreads();
        if (kt + 2 < 16) load_tile(kt + 2, kt & 1);
        CP_COMMIT();
    }

    // Epilogue: + bias + residual, write out[b][n][o] (o contiguous)
    const float* resb = ((m0 == 0) ? rgb : ir) + (size_t)b * 128 * NPIX;
    float* outb = out + (size_t)b * NPIX * 256;

    #pragma unroll
    for (int mt = 0; mt < 4; mt++) {
        const int o_lo = m0 + wm0 + mt * 16 + row;
        const int o_hi = o_lo + 8;
        const float bias_lo = __ldg(bias + o_lo);
        const float bias_hi = __ldg(bias + o_hi);
        const float* res_lo = resb + (size_t)(o_lo & 127) * NPIX;
        const float* res_hi = resb + (size_t)(o_hi & 127) * NPIX;
        #pragma unroll
        for (int nt = 0; nt < 4; nt++) {
            const int n = n0 + wn0 + nt * 8 + 2 * colk;
            outb[(size_t)n * 256 + o_lo]       = acc[mt][nt][0] + bias_lo + res_lo[n];
            outb[(size_t)(n + 1) * 256 + o_lo] = acc[mt][nt][1] + bias_lo + res_lo[n + 1];
            outb[(size_t)n * 256 + o_hi]       = acc[mt][nt][2] + bias_hi + res_hi[n];
            outb[(size_t)(n + 1) * 256 + o_hi] = acc[mt][nt][3] + bias_hi + res_hi[n + 1];
        }
    }
}

// ---------------------------------------------------------------------------
extern "C" void kernel_launch(void* const* d_in, const int* in_sizes, int n_in,
                              void* d_out, int out_size)
{
    const float* rgb    = (const float*)d_in[0];
    const float* ir     = (const float*)d_in[1];
    const float* w_qkv  = (const float*)d_in[2];
    const float* w_proj = (const float*)d_in[3];
    const float* b_proj = (const float*)d_in[4];
    float* out = (float*)d_out;

    conv_y<<<6400, 256>>>(rgb, ir);              // 4*256*6400/(256*4) blocks
    conv_w<<<1024, 256>>>(w_qkv, w_proj);
    qkv_gemm<<<dim3(50, 6, 4), 256>>>();
    attn_kernel<<<dim3(25, 8, 4), 256>>>();
    proj_kernel<<<dim3(50, 2, 4), 256>>>(b_proj, rgb, ir, out);
}